// round 4
// baseline (speedup 1.0000x reference)
#include <cuda_runtime.h>
#include <cstdint>

#define TAGS       10
#define SEQ        512
#define BATCHN     8192
#define START_TAG  8
#define STOP_TAG   9
#define NEG_INF    (-10000.0f)

#define STAGES     8
#define EPW        16                      // batch elems per warp
#define WSTAGE     (EPW * TAGS * 4)        // 640 B per warp per step
#define WPB        4                       // warps per block
#define BPB        (EPW * WPB)             // 64 elems per block

// Backpointers: one u64 per (t,b), tag n's argmax in nibble 4*n. 33.5 MB scratch.
__device__ unsigned long long g_bp[(size_t)SEQ * BATCHN];

__device__ __forceinline__ void cp16(uint32_t s_addr, const void* g) {
    asm volatile("cp.async.ca.shared.global [%0], [%1], 16;\n"
                 :: "r"(s_addr), "l"(g));
}
__device__ __forceinline__ void cp_commit() {
    asm volatile("cp.async.commit_group;\n" ::: "memory");
}
__device__ __forceinline__ void cp_wait6() {
    asm volatile("cp.async.wait_group 6;\n" ::: "memory");
}

// tournament node: value max + first-index argmax (left wins ties; exact compares)
#define TOURN(vl, il, vr, ir, mo, io) \
    { bool _p = (vr) > (vl); mo = _p ? (vr) : (vl); io = _p ? (ir) : (il); }

__global__ __launch_bounds__(128, 1)
void crf_viterbi4(const float* __restrict__ feats,
                  const float* __restrict__ trans,
                  float* __restrict__ out) {
    // warp-private rings: 4 warps x 8 stages x 640 B = 20 KB
    __shared__ __align__(16) char ring[WPB][STAGES][WSTAGE];

    const int tid   = threadIdx.x;
    const int warp  = tid >> 5;
    const int lane  = tid & 31;
    const int lb    = lane >> 1;        // local elem 0..15 within warp
    const int half  = lane & 1;         // 0: next-tags 0..4, 1: next-tags 5..9
    const int nbase = half * 5;
    const int b     = blockIdx.x * BPB + warp * EPW + lb;

    // global byte base of this warp's per-step 640B slice
    const char*  gbase = (const char*)feats +
                         ((size_t)blockIdx.x * BPB + (size_t)warp * EPW) * (TAGS * 4);
    const size_t gstep = (size_t)BATCHN * TAGS * 4;   // bytes per timestep

    // copy chunks: 40 x 16B per stage; lane copies chunk `lane`, lanes 0..7 also 32+lane
    const bool has_c1 = (lane < 8);

    uint32_t s_ring0;
    asm("{ .reg .u64 t; cvta.to.shared.u64 t, %1; cvt.u32.u64 %0, t; }"
        : "=r"(s_ring0) : "l"(&ring[warp][0][0]));

    // transitions: my 5 next-tag rows + STOP row
    float T[5][TAGS];
#pragma unroll
    for (int i = 0; i < 5; i++)
#pragma unroll
        for (int p = 0; p < TAGS; p++)
            T[i][p] = __ldg(trans + (nbase + i) * TAGS + p);
    float Ts[TAGS];
#pragma unroll
    for (int p = 0; p < TAGS; p++) Ts[p] = __ldg(trans + STOP_TAG * TAGS + p);

    float fv[TAGS];
#pragma unroll
    for (int p = 0; p < TAGS; p++) fv[p] = NEG_INF;
    fv[START_TAG] = 0.0f;

    // prologue: fill stages 0..6 (steps 0..6), one commit group per step
#pragma unroll
    for (int s = 0; s < STAGES - 1; s++) {
        const char* g = gbase + (size_t)s * gstep;
        uint32_t sb = s_ring0 + s * WSTAGE;
        cp16(sb + lane * 16, g + lane * 16);
        if (has_c1) cp16(sb + (32 + lane) * 16, g + (32 + lane) * 16);
        cp_commit();
    }

    // per-thread smem read offsets within a stage
    const int offA = lb * 40 + (half ? 24 : 0);
    const int offB = lb * 40 + (half ? 32 : 8);
    const int offS = lb * 40 + (half ? 20 : 16);

    unsigned long long* __restrict__ bp_col = g_bp + b;

#pragma unroll 4
    for (int t = 0; t < SEQ; t++) {
        cp_wait6();          // my chunks of stage t are done
        __syncwarp();        // ... and everyone else's in this warp are visible

        const char* sp = ring[warp][t & (STAGES - 1)];
        float2 A = *(const float2*)(sp + offA);
        float2 B = *(const float2*)(sp + offB);
        float  s = *(const float*)(sp + offS);
        float f[5];
        if (half) { f[0] = s;   f[1] = A.x; f[2] = A.y; f[3] = B.x; f[4] = B.y; }
        else      { f[0] = A.x; f[1] = A.y; f[2] = B.x; f[3] = B.y; f[4] = s;   }

        // prefetch step t+7 into the stage just freed; always commit to keep groups aligned
        {
            int ns = t + STAGES - 1;
            if (ns < SEQ) {
                const char* g = gbase + (size_t)ns * gstep;
                uint32_t sb = s_ring0 + (ns & (STAGES - 1)) * WSTAGE;
                cp16(sb + lane * 16, g + lane * 16);
                if (has_c1) cp16(sb + (32 + lane) * 16, g + (32 + lane) * 16);
            }
            cp_commit();
        }

        // 5 next-tags: max + first-index argmax tournament over 10 prev tags
        float nf[5];
        unsigned bits = 0u;
#pragma unroll
        for (int i = 0; i < 5; i++) {
            float v0 = fv[0] + T[i][0], v1 = fv[1] + T[i][1];
            float v2 = fv[2] + T[i][2], v3 = fv[3] + T[i][3];
            float v4 = fv[4] + T[i][4], v5 = fv[5] + T[i][5];
            float v6 = fv[6] + T[i][6], v7 = fv[7] + T[i][7];
            float v8 = fv[8] + T[i][8], v9 = fv[9] + T[i][9];
            float m01, m23, m45, m67, m89, m03, m47, m07, m;
            int   i01, i23, i45, i67, i89, i03, i47, i07, bi;
            TOURN(v0, 0, v1, 1, m01, i01);
            TOURN(v2, 2, v3, 3, m23, i23);
            TOURN(v4, 4, v5, 5, m45, i45);
            TOURN(v6, 6, v7, 7, m67, i67);
            TOURN(v8, 8, v9, 9, m89, i89);
            TOURN(m01, i01, m23, i23, m03, i03);
            TOURN(m45, i45, m67, i67, m47, i47);
            TOURN(m03, i03, m47, i47, m07, i07);
            TOURN(m07, i07, m89, i89, m,   bi);
            nf[i] = m + f[i];
            bits |= (unsigned)bi << (4 * i);
        }

        // lane-pair exchange of the other half's new fv
#pragma unroll
        for (int i = 0; i < 5; i++) {
            float o = __shfl_xor_sync(0xffffffffu, nf[i], 1);
            fv[i]     = half ? o     : nf[i];
            fv[i + 5] = half ? nf[i] : o;
        }
        unsigned obits = __shfl_xor_sync(0xffffffffu, bits, 1);
        if (!half) {
            unsigned long long w =
                (unsigned long long)bits | ((unsigned long long)obits << 20);
            bp_col[(size_t)t * BATCHN] = w;   // 16 consecutive u64 per warp
        }
    }

    // terminal: max/argmax of fv + trans[STOP]
    float tv[TAGS];
#pragma unroll
    for (int p = 0; p < TAGS; p++) tv[p] = fv[p] + Ts[p];
    float m01, m23, m45, m67, m89, m03, m47, m07, m;
    int   i01, i23, i45, i67, i89, i03, i47, i07, tag;
    TOURN(tv[0], 0, tv[1], 1, m01, i01);
    TOURN(tv[2], 2, tv[3], 3, m23, i23);
    TOURN(tv[4], 4, tv[5], 5, m45, i45);
    TOURN(tv[6], 6, tv[7], 7, m67, i67);
    TOURN(tv[8], 8, tv[9], 9, m89, i89);
    TOURN(m01, i01, m23, i23, m03, i03);
    TOURN(m45, i45, m67, i67, m47, i47);
    TOURN(m03, i03, m47, i47, m07, i07);
    TOURN(m07, i07, m89, i89, m,   tag);

    if (!half) {
        out[b] = m;
        float* __restrict__ path = out + BATCHN;
        // backtrace: loads are address-independent of tag -> deep unroll for MLP
#pragma unroll 16
        for (int t = SEQ - 1; t >= 0; t--) {
            path[(size_t)t * BATCHN + b] = (float)tag;
            unsigned long long w = bp_col[(size_t)t * BATCHN];
            tag = (int)((w >> (tag * 4)) & 0xFull);
        }
    }
}

extern "C" void kernel_launch(void* const* d_in, const int* in_sizes, int n_in,
                              void* d_out, int out_size) {
    const float* feats = (const float*)d_in[0];
    const float* trans = (const float*)d_in[1];
    float* out = (float*)d_out;

    crf_viterbi4<<<BATCHN / BPB, 128>>>(feats, trans, out);   // 128 blocks x 4 warps
}